// round 6
// baseline (speedup 1.0000x reference)
#include <cuda_runtime.h>
#include <cuda_bf16.h>
#include <math.h>
#include <stdint.h>

#define SQ   2048
#define DIM  1024
#define NH   16
#define HD   64
#define NROT 32

#define SCALE_QK 0.35355339059327373f          // 64^-0.25
#define SCALE_LG 0.47855339059327373f          // 64^-0.5 + 64^-0.25

// ---------------- scratch (no allocation allowed) ----------------
__device__ float d_M[HD * HD];
__device__ float d_Wq2[DIM * DIM];
__device__ float d_Wk2[DIM * DIM];
__device__ float d_bq2[DIM];
__device__ float d_q[SQ * DIM];
__device__ float d_k[SQ * DIM];
__device__ float d_v[SQ * DIM];
__device__ float d_a[SQ * DIM];
__device__ __nv_bfloat16 d_Ahi[SQ * DIM];
__device__ __nv_bfloat16 d_Alo[SQ * DIM];
__device__ __nv_bfloat16 d_WThi[4 * DIM * DIM];
__device__ __nv_bfloat16 d_WTlo[4 * DIM * DIM];
// head-major bf16 hi/lo for flash: [(h*SQ + s)*HD + d]
__device__ __nv_bfloat16 d_fqhi[NH * SQ * HD];
__device__ __nv_bfloat16 d_fqlo[NH * SQ * HD];
__device__ __nv_bfloat16 d_fkhi[NH * SQ * HD];
__device__ __nv_bfloat16 d_fklo[NH * SQ * HD];
__device__ __nv_bfloat16 d_fvhi[NH * SQ * HD];
__device__ __nv_bfloat16 d_fvlo[NH * SQ * HD];

// ================= PTX helpers (arch-agnostic: ldmatrix + mma.sync) ========
__device__ __forceinline__ uint32_t smem_u32(const void* p) {
    uint32_t a;
    asm("{ .reg .u64 t; cvta.to.shared.u64 t, %1; cvt.u32.u64 %0, t; }" : "=r"(a) : "l"(p));
    return a;
}
__device__ __forceinline__ void ldmatrix_x4(uint32_t* r, uint32_t addr) {
    asm volatile("ldmatrix.sync.aligned.m8n8.x4.shared.b16 {%0,%1,%2,%3}, [%4];"
                 : "=r"(r[0]), "=r"(r[1]), "=r"(r[2]), "=r"(r[3]) : "r"(addr));
}
__device__ __forceinline__ void ldmatrix_x2(uint32_t* r, uint32_t addr) {
    asm volatile("ldmatrix.sync.aligned.m8n8.x2.shared.b16 {%0,%1}, [%2];"
                 : "=r"(r[0]), "=r"(r[1]) : "r"(addr));
}
__device__ __forceinline__ void ldmatrix_x2_trans(uint32_t* r, uint32_t addr) {
    asm volatile("ldmatrix.sync.aligned.m8n8.x2.trans.shared.b16 {%0,%1}, [%2];"
                 : "=r"(r[0]), "=r"(r[1]) : "r"(addr));
}
__device__ __forceinline__ void mma_bf16(float* d, const uint32_t* a, const uint32_t* b) {
    asm volatile(
        "mma.sync.aligned.m16n8k16.row.col.f32.bf16.bf16.f32 "
        "{%0,%1,%2,%3}, {%4,%5,%6,%7}, {%8,%9}, {%0,%1,%2,%3};"
        : "+f"(d[0]), "+f"(d[1]), "+f"(d[2]), "+f"(d[3])
        : "r"(a[0]), "r"(a[1]), "r"(a[2]), "r"(a[3]), "r"(b[0]), "r"(b[1]));
}
__device__ __forceinline__ uint32_t pack_hi_lo(float a, float b, float* la, float* lb) {
    __nv_bfloat162 h = __floats2bfloat162_rn(a, b);
    *la = a - __bfloat162float(h.x);
    *lb = b - __bfloat162float(h.y);
    return *reinterpret_cast<uint32_t*>(&h);
}
__device__ __forceinline__ uint32_t pack2(float a, float b) {
    __nv_bfloat162 h = __floats2bfloat162_rn(a, b);
    return *reinterpret_cast<uint32_t*>(&h);
}
__device__ __forceinline__ void cp16(uint32_t dst, const void* src) {
    asm volatile("cp.async.cg.shared.global [%0], [%1], 16;" :: "r"(dst), "l"(src));
}

// ---------------- M = G_total @ rotation_matrix ----------------
__global__ void compute_M_kernel(const float* __restrict__ thetas,
                                 const float* __restrict__ theta_scale,
                                 const float* __restrict__ rotmat,
                                 const int*   __restrict__ rot_idx) {
    __shared__ float G[HD][HD];
    int t = threadIdx.x;
    for (int c = 0; c < HD; c++) G[t][c] = (t == c) ? 1.0f : 0.0f;
    float ts = theta_scale[0];
    for (int r = 0; r < NROT; r++) {
        float th = thetas[r] * ts;
        float cs = cosf(th), sn = sinf(th);
        int i = rot_idx[2 * r], j = rot_idx[2 * r + 1];
        if (i != j) {
            float ai = G[t][i], aj = G[t][j];
            G[t][i] = cs * ai + sn * aj;
            G[t][j] = -sn * ai + cs * aj;
        } else {
            G[t][i] *= cs;
        }
    }
    __syncthreads();
    for (int c = 0; c < HD; c++) {
        float acc = 0.0f;
        for (int e = 0; e < HD; e++) acc += G[t][e] * rotmat[e * HD + c];
        d_M[t * HD + c] = acc;
    }
}

// ---------------- fold M into Wq / Wk columns (per head) ----------------
__global__ void fold_W_kernel(const float* __restrict__ Wq,
                              const float* __restrict__ Wk) {
    int d = blockIdx.x, h = blockIdx.y, which = blockIdx.z;
    int c = threadIdx.x;
    const float* W = which ? Wk : Wq;
    float* Wout = which ? d_Wk2 : d_Wq2;
    __shared__ float wrow[HD];
    wrow[c] = W[d * DIM + h * HD + c];
    __syncthreads();
    float acc = 0.0f;
#pragma unroll
    for (int e = 0; e < HD; e++) acc += wrow[e] * d_M[e * HD + c];
    Wout[d * DIM + h * HD + c] = acc;
}

__global__ void fold_b_kernel(const float* __restrict__ bq) {
    int h = blockIdx.x, c = threadIdx.x;
    float acc = 0.0f;
#pragma unroll
    for (int e = 0; e < HD; e++) acc += bq[h * HD + e] * d_M[e * HD + c];
    d_bq2[h * HD + c] = acc;
}

// ---------------- split fp32 -> bf16 hi/lo (row-major, A operand) ----------------
__global__ void split_A_kernel(const float* __restrict__ src) {
    int i = blockIdx.x * blockDim.x + threadIdx.x;
    if (i >= SQ * DIM) return;
    float v = src[i];
    __nv_bfloat16 hi = __float2bfloat16_rn(v);
    d_Ahi[i] = hi;
    d_Alo[i] = __float2bfloat16_rn(v - __bfloat162float(hi));
}

// ---------------- transpose + split weights ----------------
__global__ void split_WT_kernel(const float* __restrict__ W, int slot) {
    __shared__ float tile[32][33];
    int tx = threadIdx.x, ty = threadIdx.y;  // 32 x 8
    int bx = blockIdx.x, by = blockIdx.y;
#pragma unroll
    for (int i = 0; i < 4; i++)
        tile[ty + i * 8][tx] = W[(by * 32 + ty + i * 8) * DIM + bx * 32 + tx];
    __syncthreads();
    __nv_bfloat16* hi = d_WThi + slot * DIM * DIM;
    __nv_bfloat16* lo = d_WTlo + slot * DIM * DIM;
#pragma unroll
    for (int i = 0; i < 4; i++) {
        float v = tile[tx][ty + i * 8];
        __nv_bfloat16 h = __float2bfloat16_rn(v);
        int idx = (bx * 32 + ty + i * 8) * DIM + by * 32 + tx;
        hi[idx] = h;
        lo[idx] = __float2bfloat16_rn(v - __bfloat162float(h));
    }
}

// ---------------- HMMA GEMM, cp.async double-buffered ----------------
// CTA tile 128x128, K-chunk 32, 8 warps (2m x 4n), warp tile 64x32.
#define KC 32
#define LDS_ROW 40                                 // bf16 per row (32 + 8 pad)
#define GT_TILE_B (128 * LDS_ROW * 2)              // 10240 B per operand tile
#define GT_STAGE_B (4 * GT_TILE_B)                 // 40960 B per stage
#define GT_SMEM (2 * GT_STAGE_B)                   // 81920 B
__global__ void __launch_bounds__(256, 1)
gemm_mma_kernel(const __nv_bfloat16* __restrict__ Ahi,
                const __nv_bfloat16* __restrict__ Alo,
                const __nv_bfloat16* __restrict__ BThi,
                const __nv_bfloat16* __restrict__ BTlo,
                const float* __restrict__ bias,
                float* __restrict__ C) {
    extern __shared__ char gsm[];
    const int tid = threadIdx.x;
    const int wid = tid >> 5, lane = tid & 31;
    const int wm = wid >> 2, wn = wid & 3;
    const int m0 = blockIdx.y * 128, n0 = blockIdx.x * 128;
    const uint32_t sbase = smem_u32(gsm);

    const int la16 = lane & 15, lasel = lane >> 4;
    const int lb8 = lane & 7, lbsel = (lane >> 3) & 1;
    const int ldr = tid >> 2, ldq = tid & 3;

    // issue one K-chunk into stage st
    auto issue = [&](int ch, int st) {
        const int kg = ch * KC;
        uint32_t sb = sbase + st * GT_STAGE_B;
        uint32_t soff = (uint32_t)(ldr * LDS_ROW + ldq * 8) * 2;
        uint32_t soff2 = (uint32_t)((ldr + 64) * LDS_ROW + ldq * 8) * 2;
        size_t g1 = (size_t)(m0 + ldr) * DIM + kg + ldq * 8;
        size_t g2 = (size_t)(m0 + ldr + 64) * DIM + kg + ldq * 8;
        size_t h1 = (size_t)(n0 + ldr) * DIM + kg + ldq * 8;
        size_t h2 = (size_t)(n0 + ldr + 64) * DIM + kg + ldq * 8;
        cp16(sb + soff, Ahi + g1);
        cp16(sb + soff2, Ahi + g2);
        cp16(sb + GT_TILE_B + soff, Alo + g1);
        cp16(sb + GT_TILE_B + soff2, Alo + g2);
        cp16(sb + 2 * GT_TILE_B + soff, BThi + h1);
        cp16(sb + 2 * GT_TILE_B + soff2, BThi + h2);
        cp16(sb + 3 * GT_TILE_B + soff, BTlo + h1);
        cp16(sb + 3 * GT_TILE_B + soff2, BTlo + h2);
        asm volatile("cp.async.commit_group;" ::: "memory");
    };

    float acc[4][4][4] = {};

    issue(0, 0);
    issue(1, 1);

    const int NCH = DIM / KC;  // 32
    for (int ch = 0; ch < NCH; ch++) {
        const int st = ch & 1;
        asm volatile("cp.async.wait_group 1;" ::: "memory");
        __syncthreads();

        uint32_t sAh_b = sbase + st * GT_STAGE_B;
        uint32_t sAl_b = sAh_b + GT_TILE_B;
        uint32_t sBh_b = sAh_b + 2 * GT_TILE_B;
        uint32_t sBl_b = sAh_b + 3 * GT_TILE_B;

#pragma unroll
        for (int kf = 0; kf < 2; kf++) {
            uint32_t ah[4][4], al[4][4], bh[4][2], bl[4][2];
#pragma unroll
            for (int mf = 0; mf < 4; mf++) {
                uint32_t off = (uint32_t)((wm * 64 + mf * 16 + la16) * LDS_ROW +
                                          kf * 16 + lasel * 8) * 2;
                ldmatrix_x4(ah[mf], sAh_b + off);
                ldmatrix_x4(al[mf], sAl_b + off);
            }
#pragma unroll
            for (int nf = 0; nf < 4; nf++) {
                uint32_t off = (uint32_t)((wn * 32 + nf * 8 + lb8) * LDS_ROW +
                                          kf * 16 + lbsel * 8) * 2;
                ldmatrix_x2(bh[nf], sBh_b + off);
                ldmatrix_x2(bl[nf], sBl_b + off);
            }
#pragma unroll
            for (int mf = 0; mf < 4; mf++)
#pragma unroll
                for (int nf = 0; nf < 4; nf++) {
                    mma_bf16(acc[mf][nf], ah[mf], bh[nf]);
                    mma_bf16(acc[mf][nf], ah[mf], bl[nf]);
                    mma_bf16(acc[mf][nf], al[mf], bh[nf]);
                }
        }
        __syncthreads();
        if (ch + 2 < NCH) issue(ch + 2, st);
    }

    const int fr = lane >> 2, fc = (lane & 3) * 2;
#pragma unroll
    for (int mf = 0; mf < 4; mf++) {
#pragma unroll
        for (int nf = 0; nf < 4; nf++) {
            int gr = m0 + wm * 64 + mf * 16 + fr;
            int gc = n0 + wn * 32 + nf * 8 + fc;
            float b0 = bias ? bias[gc] : 0.0f;
            float b1 = bias ? bias[gc + 1] : 0.0f;
            float2 v0 = make_float2(acc[mf][nf][0] + b0, acc[mf][nf][1] + b1);
            float2 v1 = make_float2(acc[mf][nf][2] + b0, acc[mf][nf][3] + b1);
            *(float2*)&C[(size_t)gr * DIM + gc] = v0;
            *(float2*)&C[(size_t)(gr + 8) * DIM + gc] = v1;
        }
    }
}

// ---------------- RoPE (interleaved -> split halves) + pos scaling ----------------
__global__ void rope_kernel(const float* __restrict__ inv_freq,
                            const float* __restrict__ pos_scale) {
    int idx = blockIdx.x * blockDim.x + threadIdx.x;
    if (idx >= 2 * SQ * NH) return;
    int which = idx >= SQ * NH;
    int row = which ? idx - SQ * NH : idx;
    int s = row / NH, h = row % NH;
    float* t = (which ? d_k : d_q) + s * DIM + h * HD;
    float ps = pos_scale[0];
    float buf[HD];
#pragma unroll
    for (int c = 0; c < HD; c++) buf[c] = t[c];
#pragma unroll
    for (int c = 0; c < NROT; c++) {
        float ang = (float)s * inv_freq[c];
        float sn, cs;
        sincosf(ang, &sn, &cs);
        float x1 = buf[2 * c], x2 = buf[2 * c + 1];
        t[c]        = (x1 * cs - x2 * sn) * ps;
        t[c + NROT] = (x1 * sn + x2 * cs) * ps;
    }
}

// ---------------- split q/k/v into head-major bf16 hi/lo ----------------
__global__ void split_heads_kernel() {
    int gw = (blockIdx.x * blockDim.x + threadIdx.x) >> 5;
    int lane = threadIdx.x & 31;
    if (gw >= 3 * SQ * NH) return;
    int tn = gw / (SQ * NH);
    int rem = gw % (SQ * NH);
    int s = rem / NH, h = rem % NH;
    const float* src = (tn == 0 ? d_q : tn == 1 ? d_k : d_v) + (size_t)s * DIM + h * HD;
    __nv_bfloat16* dhi = (tn == 0 ? d_fqhi : tn == 1 ? d_fkhi : d_fvhi);
    __nv_bfloat16* dlo = (tn == 0 ? d_fqlo : tn == 1 ? d_fklo : d_fvlo);
    float a = src[lane * 2], b = src[lane * 2 + 1];
    __nv_bfloat162 hh = __floats2bfloat162_rn(a, b);
    __nv_bfloat162 ll = __floats2bfloat162_rn(a - __bfloat162float(hh.x),
                                              b - __bfloat162float(hh.y));
    size_t base = ((size_t)h * SQ + s) * HD + lane * 2;
    *(__nv_bfloat162*)&dhi[base] = hh;
    *(__nv_bfloat162*)&dlo[base] = ll;
}

// ---------------- flash attention on mma.sync (hi/lo 3-term) ----------------
#define FB_STRIDE 72
#define FB_TILE   (64 * FB_STRIDE * 2)
#define FB_BUF    (4 * FB_TILE)
#define FL2_SMEM  (8192 + 2 * FB_BUF)

__global__ void __launch_bounds__(256, 1)
flash_mma_kernel(const float* __restrict__ relb_g, float* __restrict__ a_out) {
    extern __shared__ char sm[];
    float* relb = (float*)sm;
    char* b0 = sm + 8192;
    char* b1 = sm + 8192 + FB_BUF;
    const int h = blockIdx.y;
    const int q0 = blockIdx.x * 128;
    const int tid = threadIdx.x, wid = tid >> 5, lane = tid & 31;

    for (int i = tid; i < 2047; i += 256) relb[i] = relb_g[i * NH + h];

    const __nv_bfloat16* qh_g = d_fqhi + ((size_t)h * SQ + q0) * HD;
    const __nv_bfloat16* ql_g = d_fqlo + ((size_t)h * SQ + q0) * HD;
#pragma unroll
    for (int i = 0; i < 4; i++) {
        int idx = tid + i * 256;
        int r = idx >> 3, c4 = idx & 7;
        *(uint4*)(b0 + r * 144 + c4 * 16) = *(const uint4*)(qh_g + r * 64 + c4 * 8);
        *(uint4*)(b0 + 18432 + r * 144 + c4 * 16) = *(const uint4*)(ql_g + r * 64 + c4 * 8);
    }
    __syncthreads();

    const __nv_bfloat16* kh_g = d_fkhi + (size_t)h * SQ * HD;
    const __nv_bfloat16* kl_g = d_fklo + (size_t)h * SQ * HD;
    const __nv_bfloat16* vh_g = d_fvhi + (size_t)h * SQ * HD;
    const __nv_bfloat16* vl_g = d_fvlo + (size_t)h * SQ * HD;

    auto issue_tile = [&](int kt, char* dst) {
        const __nv_bfloat16* srcs[4] = {kh_g + kt * 64 * HD, kl_g + kt * 64 * HD,
                                        vh_g + kt * 64 * HD, vl_g + kt * 64 * HD};
        uint32_t db = smem_u32(dst);
#pragma unroll
        for (int i = 0; i < 8; i++) {
            int idx = tid + i * 256;
            int t = idx >> 9, rem = idx & 511, r = rem >> 3, c4 = rem & 7;
            uint32_t d = db + t * FB_TILE + r * 144 + c4 * 16;
            cp16(d, srcs[t] + r * 64 + c4 * 8);
        }
        asm volatile("cp.async.commit_group;" ::: "memory");
    };

    issue_tile(0, b1);

    uint32_t qfh[4][4], qfl[4][4];
    {
        uint32_t qb = smem_u32(b0);
        int arow = wid * 16 + (lane & 15);
        int acol = (lane >> 4) * 8;
#pragma unroll
        for (int ks = 0; ks < 4; ks++) {
            uint32_t off = (uint32_t)arow * 144 + (uint32_t)(ks * 16 + acol) * 2;
            ldmatrix_x4(qfh[ks], qb + off);
            ldmatrix_x4(qfl[ks], qb + 18432 + off);
        }
    }

    float oacc[8][4] = {};
    float m0r = -1e30f, m1r = -1e30f, l0r = 0.0f, l1r = 0.0f;
    const int qg0 = q0 + wid * 16 + (lane >> 2);
    const int qg1 = qg0 + 8;

    for (int kt = 0; kt < 32; kt++) {
        char* cb = (kt & 1) ? b0 : b1;
        asm volatile("cp.async.wait_group 0;" ::: "memory");
        __syncthreads();
        if (kt + 1 < 32) issue_tile(kt + 1, (kt & 1) ? b1 : b0);

        uint32_t kb = smem_u32(cb);
        uint32_t klb = kb + FB_TILE;
        uint32_t vhb = kb + 2 * FB_TILE, vlb = kb + 3 * FB_TILE;

        float sacc[8][4] = {};
#pragma unroll
        for (int ks = 0; ks < 4; ks++) {
#pragma unroll
            for (int nf = 0; nf < 8; nf++) {
                uint32_t bh[2], bl[2];
                uint32_t boff = (uint32_t)(nf * 8 + (lane & 7)) * 144 +
                                (uint32_t)(ks * 16 + ((lane >> 3) & 1) * 8) * 2;
                ldmatrix_x2(bh, kb + boff);
                ldmatrix_x2(bl, klb + boff);
                mma_bf16(sacc[nf], qfh[ks], bh);
                mma_bf16(sacc[nf], qfl[ks], bh);
                mma_bf16(sacc[nf], qfh[ks], bl);
            }
        }

        const int k0 = kt * 64;
        float mx0 = m0r, mx1 = m1r;
#pragma unroll
        for (int nf = 0; nf < 8; nf++) {
            int kg = k0 + nf * 8 + (lane & 3) * 2;
            int p00 = min(max(qg0 - kg, -1023), 1023) + 1023;
            int p01 = min(max(qg0 - kg - 1, -1023), 1023) + 1023;
            int p10 = min(max(qg1 - kg, -1023), 1023) + 1023;
            int p11 = min(max(qg1 - kg - 1, -1023), 1023) + 1023;
            sacc[nf][0] = fmaf(sacc[nf][0], SCALE_LG, relb[p00]);
            sacc[nf][1] = fmaf(sacc[nf][1], SCALE_LG, relb[p01]);
            sacc[nf][2] = fmaf(sacc[nf][2], SCALE_LG, relb[p10]);
            sacc[nf][3] = fmaf(sacc[nf][3], SCALE_LG, relb[p11]);
            mx0 = fmaxf(mx0, fmaxf(sacc[nf][0], sacc[nf][1]));
            mx1 = fmaxf(mx1, fmaxf(sacc[nf][2], sacc[nf][3]));
        }
        mx0 = fmaxf(mx0, __shfl_xor_sync(0xffffffffu, mx0, 1));
        mx0 = fmaxf(mx0, __shfl_xor_sync(0xffffffffu, mx0, 2));
        mx1 = fmaxf(mx1, __shfl_xor_sync(0xffffffffu, mx1, 1));
        mx1 = fmaxf(mx1, __shfl_xor_sync(0xffffffffu, mx1, 2));
        float sc0 = __expf(m0r - mx0), sc1 = __expf(m1r - mx1);
        m0r = mx0; m1r = mx1;
        float s0 = 0.0f, s1 = 0.0f;
#pragma unroll
        for (int nf = 0; nf < 8; nf++) {
            sacc[nf][0] = __expf(sacc[nf][0] - mx0);
            sacc[nf][1] = __expf(sacc[nf][1] - mx0);
            sacc[nf][2] = __expf(sacc[nf][2] - mx1);
            sacc[nf][3] = __expf(sacc[nf][3] - mx1);
            s0 += sacc[nf][0] + sacc[nf][1];
            s1 += sacc[nf][2] + sacc[nf][3];
        }
        s0 += __shfl_xor_sync(0xffffffffu, s0, 1);
        s0 += __shfl_xor_sync(0xffffffffu, s0, 2);
        s1 += __shfl_xor_sync(0xffffffffu, s1, 1);
        s1 += __shfl_xor_sync(0xffffffffu, s1, 2);
        l0r = l0r * sc0 + s0;
        l1r = l1r * sc1 + s1;
#pragma unroll
        for (int nf = 0; nf < 8; nf++) {
            oacc[nf][0] *= sc0; oacc[nf][1] *= sc0;
            oacc[nf][2] *= sc1; oacc[nf][3] *= sc1;
        }

#pragma unroll
        for (int j = 0; j < 4; j++) {
            uint32_t ahi[4], alo[4];
            float x0, x1, x2, x3, x4, x5, x6, x7;
            ahi[0] = pack_hi_lo(sacc[2 * j][0], sacc[2 * j][1], &x0, &x1);
            ahi[1] = pack_hi_lo(sacc[2 * j][2], sacc[2 * j][3], &x2, &x3);
            ahi[2] = pack_hi_lo(sacc[2 * j + 1][0], sacc[2 * j + 1][1], &x4, &x5);
            ahi[3] = pack_hi_lo(sacc[2 * j + 1][2], sacc[2 * j + 1][3], &x6, &x7);
            alo[0] = pack2(x0, x1); alo[1] = pack2(x2, x3);
            alo[2] = pack2(x4, x5); alo[3] = pack2(x6, x7);
#pragma unroll
            for (int nfo = 0; nfo < 8; nfo++) {
                uint32_t bh[2], bl[2];
                uint32_t voff = (uint32_t)(j * 16 + (lane & 15)) * 144 +
                                (uint32_t)(nfo * 8) * 2;
                ldmatrix_x2_trans(bh, vhb + voff);
                ldmatrix_x2_trans(bl, vlb + voff);
                mma_bf16(oacc[nfo], ahi, bh);
                mma_bf16(oacc[nfo], ahi, bl);
                mma_bf16(oacc[nfo], alo, bh);
            }
        }
    }

    float inv0 = 1.0f / l0r, inv1 = 1.0f / l1r;
    int row0 = q0 + wid * 16 + (lane >> 2), row1 = row0 + 8;
    int colb = h * HD + (lane & 3) * 2;
#pragma unroll
    for (int nf = 0; nf < 8; nf++) {
        float2 v0 = make_float2(oacc[nf][0] * inv0, oacc[nf][1] * inv0);
        float2 v1 = make_float2(oacc[nf][2] * inv1, oacc[nf][3] * inv1);
        *(float2*)&a_out[(size_t)row0 * DIM + colb + nf * 8] = v0;
        *(float2*)&a_out[(size_t)row1 * DIM + colb + nf * 8] = v1;
    }
}

// ---------------- qk side output: attn_scores[h, 16*i, k<1024] ----------------
__global__ void qk_kernel(const float* __restrict__ relb_g,
                          float* __restrict__ qk_out) {
    int h = blockIdx.y, qi = blockIdx.x;
    int qrow = qi * 16;
    __shared__ float qv[HD];
    if (threadIdx.x < HD) qv[threadIdx.x] = d_q[qrow * DIM + h * HD + threadIdx.x];
    __syncthreads();
    for (int kk = threadIdx.x; kk < 1024; kk += 256) {
        float acc = 0.0f;
#pragma unroll
        for (int c = 0; c < HD; c++) acc += qv[c] * d_k[kk * DIM + h * HD + c];
        int p = qrow - kk;
        p = min(max(p, -1023), 1023) + 1023;
        qk_out[(h * 128 + qi) * 1024 + kk] = acc * SCALE_QK + relb_g[p * NH + h];
    }
}

// ---------------- launch ----------------
extern "C" void kernel_launch(void* const* d_in, const int* in_sizes, int n_in,
                              void* d_out, int out_size) {
    const float* x      = (const float*)d_in[0];
    const float* Wq     = (const float*)d_in[1];
    const float* bq     = (const float*)d_in[2];
    const float* Wk     = (const float*)d_in[3];
    const float* Wv     = (const float*)d_in[4];
    const float* bv     = (const float*)d_in[5];
    const float* Wo     = (const float*)d_in[6];
    const float* bo     = (const float*)d_in[7];
    const float* thetas = (const float*)d_in[8];
    const float* tscale = (const float*)d_in[9];
    const float* rotmat = (const float*)d_in[10];
    const float* invfrq = (const float*)d_in[11];
    const float* pscale = (const float*)d_in[12];
    const float* relb   = (const float*)d_in[13];
    const int*   rotidx = (const int*)d_in[14];

    float* out = (float*)d_out;
    float* qk  = out + SQ * DIM;

    float *pWq2, *pWk2, *pbq2, *pq, *pk, *pv, *pa;
    __nv_bfloat16 *pAhi, *pAlo, *pWThi, *pWTlo;
    cudaGetSymbolAddress((void**)&pWq2, d_Wq2);
    cudaGetSymbolAddress((void**)&pWk2, d_Wk2);
    cudaGetSymbolAddress((void**)&pbq2, d_bq2);
    cudaGetSymbolAddress((void**)&pq,  d_q);
    cudaGetSymbolAddress((void**)&pk,  d_k);
    cudaGetSymbolAddress((void**)&pv,  d_v);
    cudaGetSymbolAddress((void**)&pa,  d_a);
    cudaGetSymbolAddress((void**)&pAhi, d_Ahi);
    cudaGetSymbolAddress((void**)&pAlo, d_Alo);
    cudaGetSymbolAddress((void**)&pWThi, d_WThi);
    cudaGetSymbolAddress((void**)&pWTlo, d_WTlo);

    cudaFuncSetAttribute(flash_mma_kernel, cudaFuncAttributeMaxDynamicSharedMemorySize,
                         FL2_SMEM);
    cudaFuncSetAttribute(gemm_mma_kernel, cudaFuncAttributeMaxDynamicSharedMemorySize,
                         GT_SMEM);

    // prep: fold M, transpose+split weights, split x
    compute_M_kernel<<<1, 64>>>(thetas, tscale, rotmat, rotidx);
    fold_W_kernel<<<dim3(DIM, NH, 2), 64>>>(Wq, Wk);
    fold_b_kernel<<<NH, 64>>>(bq);

    dim3 tg(32, 32), tb(32, 8);
    split_WT_kernel<<<tg, tb>>>(pWq2, 0);
    split_WT_kernel<<<tg, tb>>>(pWk2, 1);
    split_WT_kernel<<<tg, tb>>>(Wv, 2);
    split_WT_kernel<<<tg, tb>>>(Wo, 3);
    split_A_kernel<<<(SQ * DIM + 255) / 256, 256>>>(x);

    // projections on HMMA tensor cores (pipelined)
    dim3 gg(DIM / 128, SQ / 128);
    gemm_mma_kernel<<<gg, 256, GT_SMEM>>>(pAhi, pAlo, pWThi + 0 * DIM * DIM, pWTlo + 0 * DIM * DIM, pbq2, pq);
    gemm_mma_kernel<<<gg, 256, GT_SMEM>>>(pAhi, pAlo, pWThi + 1 * DIM * DIM, pWTlo + 1 * DIM * DIM, nullptr, pk);
    gemm_mma_kernel<<<gg, 256, GT_SMEM>>>(pAhi, pAlo, pWThi + 2 * DIM * DIM, pWTlo + 2 * DIM * DIM, bv, pv);

    rope_kernel<<<(2 * SQ * NH + 255) / 256, 256>>>(invfrq, pscale);
    split_heads_kernel<<<(3 * SQ * NH * 32) / 256, 256>>>();

    flash_mma_kernel<<<dim3(SQ / 128, NH), 256, FL2_SMEM>>>(relb, pa);
    qk_kernel<<<dim3(128, NH), 256>>>(relb, qk);

    // output projection
    split_A_kernel<<<(SQ * DIM + 255) / 256, 256>>>(pa);
    gemm_mma_kernel<<<gg, 256, GT_SMEM>>>(pAhi, pAlo, pWThi + 3 * DIM * DIM, pWTlo + 3 * DIM * DIM, bo, out);
}

// round 7
// speedup vs baseline: 1.5672x; 1.5672x over previous
#include <cuda_runtime.h>
#include <cuda_bf16.h>
#include <math.h>
#include <stdint.h>

#define SQ   2048
#define DIM  1024
#define NH   16
#define HD   64
#define NROT 32

#define SCALE_QK 0.35355339059327373f          // 64^-0.25
#define SCALE_LG 0.47855339059327373f          // 64^-0.5 + 64^-0.25

// ---------------- scratch (no allocation allowed) ----------------
__device__ float d_M[HD * HD];
__device__ float d_Wq2[DIM * DIM];
__device__ float d_Wk2[DIM * DIM];
__device__ float d_bq2[DIM];
__device__ float d_q[SQ * DIM];
__device__ float d_k[SQ * DIM];
__device__ float d_v[SQ * DIM];
__device__ float d_a[SQ * DIM];
__device__ __nv_bfloat16 d_Ahi[SQ * DIM];
__device__ __nv_bfloat16 d_Alo[SQ * DIM];
__device__ __nv_bfloat16 d_WThi[4 * DIM * DIM];
__device__ __nv_bfloat16 d_WTlo[4 * DIM * DIM];
// head-major bf16 hi/lo for flash: [(h*SQ + s)*HD + d]
__device__ __nv_bfloat16 d_fqhi[NH * SQ * HD];
__device__ __nv_bfloat16 d_fqlo[NH * SQ * HD];
__device__ __nv_bfloat16 d_fkhi[NH * SQ * HD];
__device__ __nv_bfloat16 d_fklo[NH * SQ * HD];
__device__ __nv_bfloat16 d_fvhi[NH * SQ * HD];
__device__ __nv_bfloat16 d_fvlo[NH * SQ * HD];

// ================= PTX helpers (arch-agnostic: ldmatrix + mma.sync) ========
__device__ __forceinline__ uint32_t smem_u32(const void* p) {
    uint32_t a;
    asm("{ .reg .u64 t; cvta.to.shared.u64 t, %1; cvt.u32.u64 %0, t; }" : "=r"(a) : "l"(p));
    return a;
}
__device__ __forceinline__ void ldmatrix_x4(uint32_t* r, uint32_t addr) {
    asm volatile("ldmatrix.sync.aligned.m8n8.x4.shared.b16 {%0,%1,%2,%3}, [%4];"
                 : "=r"(r[0]), "=r"(r[1]), "=r"(r[2]), "=r"(r[3]) : "r"(addr));
}
__device__ __forceinline__ void ldmatrix_x2(uint32_t* r, uint32_t addr) {
    asm volatile("ldmatrix.sync.aligned.m8n8.x2.shared.b16 {%0,%1}, [%2];"
                 : "=r"(r[0]), "=r"(r[1]) : "r"(addr));
}
__device__ __forceinline__ void ldmatrix_x2_trans(uint32_t* r, uint32_t addr) {
    asm volatile("ldmatrix.sync.aligned.m8n8.x2.trans.shared.b16 {%0,%1}, [%2];"
                 : "=r"(r[0]), "=r"(r[1]) : "r"(addr));
}
__device__ __forceinline__ void mma_bf16(float* d, const uint32_t* a, const uint32_t* b) {
    asm volatile(
        "mma.sync.aligned.m16n8k16.row.col.f32.bf16.bf16.f32 "
        "{%0,%1,%2,%3}, {%4,%5,%6,%7}, {%8,%9}, {%0,%1,%2,%3};"
        : "+f"(d[0]), "+f"(d[1]), "+f"(d[2]), "+f"(d[3])
        : "r"(a[0]), "r"(a[1]), "r"(a[2]), "r"(a[3]), "r"(b[0]), "r"(b[1]));
}
__device__ __forceinline__ uint32_t pack_hi_lo(float a, float b, float* la, float* lb) {
    __nv_bfloat162 h = __floats2bfloat162_rn(a, b);
    *la = a - __bfloat162float(h.x);
    *lb = b - __bfloat162float(h.y);
    return *reinterpret_cast<uint32_t*>(&h);
}
__device__ __forceinline__ uint32_t pack2(float a, float b) {
    __nv_bfloat162 h = __floats2bfloat162_rn(a, b);
    return *reinterpret_cast<uint32_t*>(&h);
}
__device__ __forceinline__ void cp16(uint32_t dst, const void* src) {
    asm volatile("cp.async.cg.shared.global [%0], [%1], 16;" :: "r"(dst), "l"(src));
}

// ---------------- M = G_total @ rotation_matrix ----------------
__global__ void compute_M_kernel(const float* __restrict__ thetas,
                                 const float* __restrict__ theta_scale,
                                 const float* __restrict__ rotmat,
                                 const int*   __restrict__ rot_idx) {
    __shared__ float G[HD][HD];
    int t = threadIdx.x;
    for (int c = 0; c < HD; c++) G[t][c] = (t == c) ? 1.0f : 0.0f;
    float ts = theta_scale[0];
    for (int r = 0; r < NROT; r++) {
        float th = thetas[r] * ts;
        float cs = cosf(th), sn = sinf(th);
        int i = rot_idx[2 * r], j = rot_idx[2 * r + 1];
        if (i != j) {
            float ai = G[t][i], aj = G[t][j];
            G[t][i] = cs * ai + sn * aj;
            G[t][j] = -sn * ai + cs * aj;
        } else {
            G[t][i] *= cs;
        }
    }
    __syncthreads();
    for (int c = 0; c < HD; c++) {
        float acc = 0.0f;
        for (int e = 0; e < HD; e++) acc += G[t][e] * rotmat[e * HD + c];
        d_M[t * HD + c] = acc;
    }
}

// ---------------- fold M into Wq / Wk columns (per head) ----------------
__global__ void fold_W_kernel(const float* __restrict__ Wq,
                              const float* __restrict__ Wk) {
    int d = blockIdx.x, h = blockIdx.y, which = blockIdx.z;
    int c = threadIdx.x;
    const float* W = which ? Wk : Wq;
    float* Wout = which ? d_Wk2 : d_Wq2;
    __shared__ float wrow[HD];
    wrow[c] = W[d * DIM + h * HD + c];
    __syncthreads();
    float acc = 0.0f;
#pragma unroll
    for (int e = 0; e < HD; e++) acc += wrow[e] * d_M[e * HD + c];
    Wout[d * DIM + h * HD + c] = acc;
}

__global__ void fold_b_kernel(const float* __restrict__ bq) {
    int h = blockIdx.x, c = threadIdx.x;
    float acc = 0.0f;
#pragma unroll
    for (int e = 0; e < HD; e++) acc += bq[h * HD + e] * d_M[e * HD + c];
    d_bq2[h * HD + c] = acc;
}

// ---------------- split fp32 -> bf16 hi/lo (row-major, A operand) ----------------
__global__ void split_A_kernel(const float* __restrict__ src) {
    int i = blockIdx.x * blockDim.x + threadIdx.x;
    if (i >= SQ * DIM) return;
    float v = src[i];
    __nv_bfloat16 hi = __float2bfloat16_rn(v);
    d_Ahi[i] = hi;
    d_Alo[i] = __float2bfloat16_rn(v - __bfloat162float(hi));
}

// ---------------- transpose + split weights ----------------
__global__ void split_WT_kernel(const float* __restrict__ W, int slot) {
    __shared__ float tile[32][33];
    int tx = threadIdx.x, ty = threadIdx.y;  // 32 x 8
    int bx = blockIdx.x, by = blockIdx.y;
#pragma unroll
    for (int i = 0; i < 4; i++)
        tile[ty + i * 8][tx] = W[(by * 32 + ty + i * 8) * DIM + bx * 32 + tx];
    __syncthreads();
    __nv_bfloat16* hi = d_WThi + slot * DIM * DIM;
    __nv_bfloat16* lo = d_WTlo + slot * DIM * DIM;
#pragma unroll
    for (int i = 0; i < 4; i++) {
        float v = tile[tx][ty + i * 8];
        __nv_bfloat16 h = __float2bfloat16_rn(v);
        int idx = (bx * 32 + ty + i * 8) * DIM + by * 32 + tx;
        hi[idx] = h;
        lo[idx] = __float2bfloat16_rn(v - __bfloat162float(h));
    }
}

// ---------------- HMMA GEMM (R5-proven core), multi-output slots ----------------
// CTA tile 128x128, K-chunk 32, 8 warps (2m x 4n), warp tile 64x32.
// blockIdx.x = slot * ntile_n + nt; output/bias chosen per slot.
#define KC 32
#define LDS_ROW 40
__global__ void __launch_bounds__(256, 2)
gemm_mma_kernel(const __nv_bfloat16* __restrict__ Ahi,
                const __nv_bfloat16* __restrict__ Alo,
                const __nv_bfloat16* __restrict__ BThi,
                const __nv_bfloat16* __restrict__ BTlo,
                const float* __restrict__ bias0,
                const float* __restrict__ bias1,
                const float* __restrict__ bias2,
                float* __restrict__ C0,
                float* __restrict__ C1,
                float* __restrict__ C2) {
    __shared__ __nv_bfloat16 sAh[128 * LDS_ROW];
    __shared__ __nv_bfloat16 sAl[128 * LDS_ROW];
    __shared__ __nv_bfloat16 sBh[128 * LDS_ROW];
    __shared__ __nv_bfloat16 sBl[128 * LDS_ROW];

    const int tid = threadIdx.x;
    const int wid = tid >> 5, lane = tid & 31;
    const int wm = wid >> 2, wn = wid & 3;
    const int slot = blockIdx.x >> 3;
    const int m0 = blockIdx.y * 128;
    const int nb = (blockIdx.x & 7) * 128;          // column within slot's output
    const int ng = blockIdx.x * 128;                // row in concatenated B

    const float* bias = (slot == 0) ? bias0 : (slot == 1) ? bias1 : bias2;
    float* C = (slot == 0) ? C0 : (slot == 1) ? C1 : C2;

    const uint32_t sAh_b = smem_u32(sAh), sAl_b = smem_u32(sAl);
    const uint32_t sBh_b = smem_u32(sBh), sBl_b = smem_u32(sBl);

    const int la16 = lane & 15, lasel = lane >> 4;
    const int lb8 = lane & 7, lbsel = (lane >> 3) & 1;

    float acc[4][4][4] = {};
    const int ldr = tid >> 2, ldq = tid & 3;

    for (int ch = 0; ch < DIM / KC; ch++) {
        const int kg = ch * KC;
        __syncthreads();
#pragma unroll
        for (int i = 0; i < 2; i++) {
            int r = ldr + i * 64;
            uint4 vh = *(const uint4*)(Ahi + (size_t)(m0 + r) * DIM + kg + ldq * 8);
            uint4 vl = *(const uint4*)(Alo + (size_t)(m0 + r) * DIM + kg + ldq * 8);
            *(uint4*)(sAh + r * LDS_ROW + ldq * 8) = vh;
            *(uint4*)(sAl + r * LDS_ROW + ldq * 8) = vl;
            uint4 wh = *(const uint4*)(BThi + (size_t)(ng + r) * DIM + kg + ldq * 8);
            uint4 wl = *(const uint4*)(BTlo + (size_t)(ng + r) * DIM + kg + ldq * 8);
            *(uint4*)(sBh + r * LDS_ROW + ldq * 8) = wh;
            *(uint4*)(sBl + r * LDS_ROW + ldq * 8) = wl;
        }
        __syncthreads();

#pragma unroll
        for (int kf = 0; kf < 2; kf++) {
            uint32_t ah[4][4], al[4][4], bh[4][2], bl[4][2];
#pragma unroll
            for (int mf = 0; mf < 4; mf++) {
                uint32_t off = (uint32_t)((wm * 64 + mf * 16 + la16) * LDS_ROW +
                                          kf * 16 + lasel * 8) * 2;
                ldmatrix_x4(ah[mf], sAh_b + off);
                ldmatrix_x4(al[mf], sAl_b + off);
            }
#pragma unroll
            for (int nf = 0; nf < 4; nf++) {
                uint32_t off = (uint32_t)((wn * 32 + nf * 8 + lb8) * LDS_ROW +
                                          kf * 16 + lbsel * 8) * 2;
                ldmatrix_x2(bh[nf], sBh_b + off);
                ldmatrix_x2(bl[nf], sBl_b + off);
            }
#pragma unroll
            for (int mf = 0; mf < 4; mf++)
#pragma unroll
                for (int nf = 0; nf < 4; nf++) {
                    mma_bf16(acc[mf][nf], ah[mf], bh[nf]);
                    mma_bf16(acc[mf][nf], ah[mf], bl[nf]);
                    mma_bf16(acc[mf][nf], al[mf], bh[nf]);
                }
        }
    }

    const int fr = lane >> 2, fc = (lane & 3) * 2;
#pragma unroll
    for (int mf = 0; mf < 4; mf++) {
#pragma unroll
        for (int nf = 0; nf < 4; nf++) {
            int gr = m0 + wm * 64 + mf * 16 + fr;
            int gc = nb + wn * 32 + nf * 8 + fc;
            float b0 = bias ? bias[gc] : 0.0f;
            float b1 = bias ? bias[gc + 1] : 0.0f;
            float2 v0 = make_float2(acc[mf][nf][0] + b0, acc[mf][nf][1] + b1);
            float2 v1 = make_float2(acc[mf][nf][2] + b0, acc[mf][nf][3] + b1);
            *(float2*)&C[(size_t)gr * DIM + gc] = v0;
            *(float2*)&C[(size_t)(gr + 8) * DIM + gc] = v1;
        }
    }
}

// ---------------- RoPE (interleaved -> split halves) + pos scaling ----------------
__global__ void rope_kernel(const float* __restrict__ inv_freq,
                            const float* __restrict__ pos_scale) {
    int idx = blockIdx.x * blockDim.x + threadIdx.x;
    if (idx >= 2 * SQ * NH) return;
    int which = idx >= SQ * NH;
    int row = which ? idx - SQ * NH : idx;
    int s = row / NH, h = row % NH;
    float* t = (which ? d_k : d_q) + s * DIM + h * HD;
    float ps = pos_scale[0];
    float buf[HD];
#pragma unroll
    for (int c = 0; c < HD; c++) buf[c] = t[c];
#pragma unroll
    for (int c = 0; c < NROT; c++) {
        float ang = (float)s * inv_freq[c];
        float sn, cs;
        sincosf(ang, &sn, &cs);
        float x1 = buf[2 * c], x2 = buf[2 * c + 1];
        t[c]        = (x1 * cs - x2 * sn) * ps;
        t[c + NROT] = (x1 * sn + x2 * cs) * ps;
    }
}

// ---------------- split q/k/v into head-major bf16 hi/lo ----------------
__global__ void split_heads_kernel() {
    int gw = (blockIdx.x * blockDim.x + threadIdx.x) >> 5;
    int lane = threadIdx.x & 31;
    if (gw >= 3 * SQ * NH) return;
    int tn = gw / (SQ * NH);
    int rem = gw % (SQ * NH);
    int s = rem / NH, h = rem % NH;
    const float* src = (tn == 0 ? d_q : tn == 1 ? d_k : d_v) + (size_t)s * DIM + h * HD;
    __nv_bfloat16* dhi = (tn == 0 ? d_fqhi : tn == 1 ? d_fkhi : d_fvhi);
    __nv_bfloat16* dlo = (tn == 0 ? d_fqlo : tn == 1 ? d_fklo : d_fvlo);
    float a = src[lane * 2], b = src[lane * 2 + 1];
    __nv_bfloat162 hh = __floats2bfloat162_rn(a, b);
    __nv_bfloat162 ll = __floats2bfloat162_rn(a - __bfloat162float(hh.x),
                                              b - __bfloat162float(hh.y));
    size_t base = ((size_t)h * SQ + s) * HD + lane * 2;
    *(__nv_bfloat162*)&dhi[base] = hh;
    *(__nv_bfloat162*)&dlo[base] = ll;
}

// ---------------- flash attention on mma.sync (hi/lo 3-term) ----------------
#define FB_STRIDE 72
#define FB_TILE   (64 * FB_STRIDE * 2)
#define FB_BUF    (4 * FB_TILE)
#define FL2_SMEM  (8192 + 2 * FB_BUF)

__global__ void __launch_bounds__(256, 1)
flash_mma_kernel(const float* __restrict__ relb_g, float* __restrict__ a_out) {
    extern __shared__ char sm[];
    float* relb = (float*)sm;
    char* b0 = sm + 8192;
    char* b1 = sm + 8192 + FB_BUF;
    const int h = blockIdx.y;
    const int q0 = blockIdx.x * 128;
    const int tid = threadIdx.x, wid = tid >> 5, lane = tid & 31;

    for (int i = tid; i < 2047; i += 256) relb[i] = relb_g[i * NH + h];

    const __nv_bfloat16* qh_g = d_fqhi + ((size_t)h * SQ + q0) * HD;
    const __nv_bfloat16* ql_g = d_fqlo + ((size_t)h * SQ + q0) * HD;
#pragma unroll
    for (int i = 0; i < 4; i++) {
        int idx = tid + i * 256;
        int r = idx >> 3, c4 = idx & 7;
        *(uint4*)(b0 + r * 144 + c4 * 16) = *(const uint4*)(qh_g + r * 64 + c4 * 8);
        *(uint4*)(b0 + 18432 + r * 144 + c4 * 16) = *(const uint4*)(ql_g + r * 64 + c4 * 8);
    }
    __syncthreads();

    const __nv_bfloat16* kh_g = d_fkhi + (size_t)h * SQ * HD;
    const __nv_bfloat16* kl_g = d_fklo + (size_t)h * SQ * HD;
    const __nv_bfloat16* vh_g = d_fvhi + (size_t)h * SQ * HD;
    const __nv_bfloat16* vl_g = d_fvlo + (size_t)h * SQ * HD;

    auto issue_tile = [&](int kt, char* dst) {
        const __nv_bfloat16* srcs[4] = {kh_g + kt * 64 * HD, kl_g + kt * 64 * HD,
                                        vh_g + kt * 64 * HD, vl_g + kt * 64 * HD};
        uint32_t db = smem_u32(dst);
#pragma unroll
        for (int i = 0; i < 8; i++) {
            int idx = tid + i * 256;
            int t = idx >> 9, rem = idx & 511, r = rem >> 3, c4 = rem & 7;
            uint32_t d = db + t * FB_TILE + r * 144 + c4 * 16;
            cp16(d, srcs[t] + r * 64 + c4 * 8);
        }
        asm volatile("cp.async.commit_group;" ::: "memory");
    };

    issue_tile(0, b1);

    uint32_t qfh[4][4], qfl[4][4];
    {
        uint32_t qb = smem_u32(b0);
        int arow = wid * 16 + (lane & 15);
        int acol = (lane >> 4) * 8;
#pragma unroll
        for (int ks = 0; ks < 4; ks++) {
            uint32_t off = (uint32_t)arow * 144 + (uint32_t)(ks * 16 + acol) * 2;
            ldmatrix_x4(qfh[ks], qb + off);
            ldmatrix_x4(qfl[ks], qb + 18432 + off);
        }
    }

    float oacc[8][4] = {};
    float m0r = -1e30f, m1r = -1e30f, l0r = 0.0f, l1r = 0.0f;
    const int qg0 = q0 + wid * 16 + (lane >> 2);
    const int qg1 = qg0 + 8;

    for (int kt = 0; kt < 32; kt++) {
        char* cb = (kt & 1) ? b0 : b1;
        asm volatile("cp.async.wait_group 0;" ::: "memory");
        __syncthreads();
        if (kt + 1 < 32) issue_tile(kt + 1, (kt & 1) ? b1 : b0);

        uint32_t kb = smem_u32(cb);
        uint32_t klb = kb + FB_TILE;
        uint32_t vhb = kb + 2 * FB_TILE, vlb = kb + 3 * FB_TILE;

        float sacc[8][4] = {};
#pragma unroll
        for (int ks = 0; ks < 4; ks++) {
#pragma unroll
            for (int nf = 0; nf < 8; nf++) {
                uint32_t bh[2], bl[2];
                uint32_t boff = (uint32_t)(nf * 8 + (lane & 7)) * 144 +
                                (uint32_t)(ks * 16 + ((lane >> 3) & 1) * 8) * 2;
                ldmatrix_x2(bh, kb + boff);
                ldmatrix_x2(bl, klb + boff);
                mma_bf16(sacc[nf], qfh[ks], bh);
                mma_bf16(sacc[nf], qfl[ks], bh);
                mma_bf16(sacc[nf], qfh[ks], bl);
            }
        }

        const int k0 = kt * 64;
        float mx0 = m0r, mx1 = m1r;
#pragma unroll
        for (int nf = 0; nf < 8; nf++) {
            int kg = k0 + nf * 8 + (lane & 3) * 2;
            int p00 = min(max(qg0 - kg, -1023), 1023) + 1023;
            int p01 = min(max(qg0 - kg - 1, -1023), 1023) + 1023;
            int p10 = min(max(qg1 - kg, -1023), 1023) + 1023;
            int p11 = min(max(qg1 - kg - 1, -1023), 1023) + 1023;
            sacc[nf][0] = fmaf(sacc[nf][0], SCALE_LG, relb[p00]);
            sacc[nf][1] = fmaf(sacc[nf][1], SCALE_LG, relb[p01]);
            sacc[nf][2] = fmaf(sacc[nf][2], SCALE_LG, relb[p10]);
            sacc[nf][3] = fmaf(sacc[nf][3], SCALE_LG, relb[p11]);
            mx0 = fmaxf(mx0, fmaxf(sacc[nf][0], sacc[nf][1]));
            mx1 = fmaxf(mx1, fmaxf(sacc[nf][2], sacc[nf][3]));
        }
        mx0 = fmaxf(mx0, __shfl_xor_sync(0xffffffffu, mx0, 1));
        mx0 = fmaxf(mx0, __shfl_xor_sync(0xffffffffu, mx0, 2));
        mx1 = fmaxf(mx1, __shfl_xor_sync(0xffffffffu, mx1, 1));
        mx1 = fmaxf(mx1, __shfl_xor_sync(0xffffffffu, mx1, 2));
        float sc0 = __expf(m0r - mx0), sc1 = __expf(m1r - mx1);
        m0r = mx0; m1r = mx1;
        float s0 = 0.0f, s1 = 0.0f;
#pragma unroll
        for (int nf = 0; nf < 8; nf++) {
            sacc[nf][0] = __expf(sacc[nf][0] - mx0);
            sacc[nf][1] = __expf(sacc[nf][1] - mx0);
            sacc[nf][2] = __expf(sacc[nf][2] - mx1);
            sacc[nf][3] = __expf(sacc[nf][3] - mx1);
            s0 += sacc[nf][0] + sacc[nf][1];
            s1 += sacc[nf][2] + sacc[nf][3];
        }
        s0 += __shfl_xor_sync(0xffffffffu, s0, 1);
        s0 += __shfl_xor_sync(0xffffffffu, s0, 2);
        s1 += __shfl_xor_sync(0xffffffffu, s1, 1);
        s1 += __shfl_xor_sync(0xffffffffu, s1, 2);
        l0r = l0r * sc0 + s0;
        l1r = l1r * sc1 + s1;
#pragma unroll
        for (int nf = 0; nf < 8; nf++) {
            oacc[nf][0] *= sc0; oacc[nf][1] *= sc0;
            oacc[nf][2] *= sc1; oacc[nf][3] *= sc1;
        }

#pragma unroll
        for (int j = 0; j < 4; j++) {
            uint32_t ahi[4], alo[4];
            float x0, x1, x2, x3, x4, x5, x6, x7;
            ahi[0] = pack_hi_lo(sacc[2 * j][0], sacc[2 * j][1], &x0, &x1);
            ahi[1] = pack_hi_lo(sacc[2 * j][2], sacc[2 * j][3], &x2, &x3);
            ahi[2] = pack_hi_lo(sacc[2 * j + 1][0], sacc[2 * j + 1][1], &x4, &x5);
            ahi[3] = pack_hi_lo(sacc[2 * j + 1][2], sacc[2 * j + 1][3], &x6, &x7);
            alo[0] = pack2(x0, x1); alo[1] = pack2(x2, x3);
            alo[2] = pack2(x4, x5); alo[3] = pack2(x6, x7);
#pragma unroll
            for (int nfo = 0; nfo < 8; nfo++) {
                uint32_t bh[2], bl[2];
                uint32_t voff = (uint32_t)(j * 16 + (lane & 15)) * 144 +
                                (uint32_t)(nfo * 8) * 2;
                ldmatrix_x2_trans(bh, vhb + voff);
                ldmatrix_x2_trans(bl, vlb + voff);
                mma_bf16(oacc[nfo], ahi, bh);
                mma_bf16(oacc[nfo], ahi, bl);
                mma_bf16(oacc[nfo], alo, bh);
            }
        }
    }

    float inv0 = 1.0f / l0r, inv1 = 1.0f / l1r;
    int row0 = q0 + wid * 16 + (lane >> 2), row1 = row0 + 8;
    int colb = h * HD + (lane & 3) * 2;
#pragma unroll
    for (int nf = 0; nf < 8; nf++) {
        float2 v0 = make_float2(oacc[nf][0] * inv0, oacc[nf][1] * inv0);
        float2 v1 = make_float2(oacc[nf][2] * inv1, oacc[nf][3] * inv1);
        *(float2*)&a_out[(size_t)row0 * DIM + colb + nf * 8] = v0;
        *(float2*)&a_out[(size_t)row1 * DIM + colb + nf * 8] = v1;
    }
}

// ---------------- qk side output: attn_scores[h, 16*i, k<1024] ----------------
__global__ void qk_kernel(const float* __restrict__ relb_g,
                          float* __restrict__ qk_out) {
    int h = blockIdx.y, qi = blockIdx.x;
    int qrow = qi * 16;
    __shared__ float qv[HD];
    if (threadIdx.x < HD) qv[threadIdx.x] = d_q[qrow * DIM + h * HD + threadIdx.x];
    __syncthreads();
    for (int kk = threadIdx.x; kk < 1024; kk += 256) {
        float acc = 0.0f;
#pragma unroll
        for (int c = 0; c < HD; c++) acc += qv[c] * d_k[kk * DIM + h * HD + c];
        int p = qrow - kk;
        p = min(max(p, -1023), 1023) + 1023;
        qk_out[(h * 128 + qi) * 1024 + kk] = acc * SCALE_QK + relb_g[p * NH + h];
    }
}

// ---------------- launch ----------------
extern "C" void kernel_launch(void* const* d_in, const int* in_sizes, int n_in,
                              void* d_out, int out_size) {
    const float* x      = (const float*)d_in[0];
    const float* Wq     = (const float*)d_in[1];
    const float* bq     = (const float*)d_in[2];
    const float* Wk     = (const float*)d_in[3];
    const float* Wv     = (const float*)d_in[4];
    const float* bv     = (const float*)d_in[5];
    const float* Wo     = (const float*)d_in[6];
    const float* bo     = (const float*)d_in[7];
    const float* thetas = (const float*)d_in[8];
    const float* tscale = (const float*)d_in[9];
    const float* rotmat = (const float*)d_in[10];
    const float* invfrq = (const float*)d_in[11];
    const float* pscale = (const float*)d_in[12];
    const float* relb   = (const float*)d_in[13];
    const int*   rotidx = (const int*)d_in[14];

    float* out = (float*)d_out;
    float* qk  = out + SQ * DIM;

    float *pWq2, *pWk2, *pbq2, *pq, *pk, *pv, *pa;
    __nv_bfloat16 *pAhi, *pAlo, *pWThi, *pWTlo;
    cudaGetSymbolAddress((void**)&pWq2, d_Wq2);
    cudaGetSymbolAddress((void**)&pWk2, d_Wk2);
    cudaGetSymbolAddress((void**)&pbq2, d_bq2);
    cudaGetSymbolAddress((void**)&pq,  d_q);
    cudaGetSymbolAddress((void**)&pk,  d_k);
    cudaGetSymbolAddress((void**)&pv,  d_v);
    cudaGetSymbolAddress((void**)&pa,  d_a);
    cudaGetSymbolAddress((void**)&pAhi, d_Ahi);
    cudaGetSymbolAddress((void**)&pAlo, d_Alo);
    cudaGetSymbolAddress((void**)&pWThi, d_WThi);
    cudaGetSymbolAddress((void**)&pWTlo, d_WTlo);

    cudaFuncSetAttribute(flash_mma_kernel, cudaFuncAttributeMaxDynamicSharedMemorySize,
                         FL2_SMEM);

    // prep: fold M, transpose+split weights, split x
    compute_M_kernel<<<1, 64>>>(thetas, tscale, rotmat, rotidx);
    fold_W_kernel<<<dim3(DIM, NH, 2), 64>>>(Wq, Wk);
    fold_b_kernel<<<NH, 64>>>(bq);

    dim3 tg(32, 32), tb(32, 8);
    split_WT_kernel<<<tg, tb>>>(pWq2, 0);
    split_WT_kernel<<<tg, tb>>>(pWk2, 1);
    split_WT_kernel<<<tg, tb>>>(Wv, 2);
    split_WT_kernel<<<tg, tb>>>(Wo, 3);
    split_A_kernel<<<(SQ * DIM + 255) / 256, 256>>>(x);

    // fused QKV projection: slots 0..2 of d_WThi are contiguous (Wq', Wk', Wv)
    gemm_mma_kernel<<<dim3(24, SQ / 128), 256>>>(
        pAhi, pAlo, pWThi, pWTlo, pbq2, nullptr, bv, pq, pk, pv);

    rope_kernel<<<(2 * SQ * NH + 255) / 256, 256>>>(invfrq, pscale);
    split_heads_kernel<<<(3 * SQ * NH * 32) / 256, 256>>>();

    flash_mma_kernel<<<dim3(SQ / 128, NH), 256, FL2_SMEM>>>(relb, pa);
    qk_kernel<<<dim3(128, NH), 256>>>(relb, qk);

    // output projection (single slot)
    split_A_kernel<<<(SQ * DIM + 255) / 256, 256>>>(pa);
    gemm_mma_kernel<<<dim3(8, SQ / 128), 256>>>(
        pAhi, pAlo, pWThi + 3 * DIM * DIM, pWTlo + 3 * DIM * DIM,
        bo, bo, bo, out, out, out);
}